// round 9
// baseline (speedup 1.0000x reference)
#include <cuda_runtime.h>
#include <math.h>

typedef unsigned long long ull;

// ---- packed f32x2 helpers (sm_103a FFMA2 path; ptxas won't auto-fuse) ----
__device__ __forceinline__ ull f2mul(ull a, ull b){
    ull d; asm("mul.rn.f32x2 %0,%1,%2;" : "=l"(d) : "l"(a), "l"(b)); return d;
}
__device__ __forceinline__ ull f2fma(ull a, ull b, ull c){
    ull d; asm("fma.rn.f32x2 %0,%1,%2,%3;" : "=l"(d) : "l"(a), "l"(b), "l"(c)); return d;
}
__device__ __forceinline__ ull f2pack(float a){
    ull d; unsigned r = __float_as_uint(a);
    asm("mov.b64 %0,{%1,%1};" : "=l"(d) : "r"(r)); return d;
}
__device__ __forceinline__ float2 f2unpack(ull a){
    unsigned lo, hi;
    asm("mov.b64 {%0,%1},%2;" : "=r"(lo), "=r"(hi) : "l"(a));
    return make_float2(__uint_as_float(lo), __uint_as_float(hi));
}

// ---- MUFU fast paths ----
__device__ __forceinline__ float rsqf(float x){
    float y; asm("rsqrt.approx.f32 %0,%1;" : "=f"(y) : "f"(x)); return y;
}
__device__ __forceinline__ float ex2f(float x){
    float y; asm("ex2.approx.f32 %0,%1;" : "=f"(y) : "f"(x)); return y;
}
__device__ __forceinline__ float lg2f(float x){
    float y; asm("lg2.approx.f32 %0,%1;" : "=f"(y) : "f"(x)); return y;
}

// reduce across the 8-lane group (lanes 0-7, 8-15, ...)
__device__ __forceinline__ float red8(float v){
    v += __shfl_xor_sync(0xffffffffu, v, 1);
    v += __shfl_xor_sync(0xffffffffu, v, 2);
    v += __shfl_xor_sync(0xffffffffu, v, 4);
    return v;
}
// two interleaved 8-lane reductions (hides SHFL latency)
__device__ __forceinline__ void red8_2(float& a, float& b){
    float a1 = __shfl_xor_sync(0xffffffffu, a, 1);
    float b1 = __shfl_xor_sync(0xffffffffu, b, 1);
    a += a1; b += b1;
    float a2 = __shfl_xor_sync(0xffffffffu, a, 2);
    float b2 = __shfl_xor_sync(0xffffffffu, b, 2);
    a += a2; b += b2;
    float a4 = __shfl_xor_sync(0xffffffffu, a, 4);
    float b4 = __shfl_xor_sync(0xffffffffu, b, 4);
    a += a4; b += b4;
}

#define LOG2E 1.4426950408889634f
#define LN2   0.6931471805599453f

__global__ __launch_bounds__(128)      // 16 rows/block: 4x finer scheduling quantum
void esh_kernel(const float* __restrict__ x0,
                const float* __restrict__ u0,
                const float* __restrict__ prec,
                const float* __restrict__ eps_p,
                float* __restrict__ out,
                int B, int n_steps)
{
    const int tid = threadIdx.x;
    const int c   = tid & 7;                       // sub-row lane (0..7)
    const int row = blockIdx.x*16 + (tid >> 3);    // 16 rows per 128-thread block

    const float eps = *eps_p;
    const float ed  = eps * (0.5f/64.0f);          // e/d, e = eps/2, d = 64
    const float k1  = -ed * LOG2E;                 // exp(-ed*g) = ex2(k1*g)

    const int o0 = c*4;                            // cols [c*4,c*4+4) and +32

    // ---- per-thread state: 8 floats x, 8 floats u, 8 floats prec (packed) ----
    ull xp[4], up[4], pp[4];
    {
        const float* xb = x0 + (size_t)row*64;
        const float* ub = u0 + (size_t)row*64;
        ulonglong2 v;
        v = *(const ulonglong2*)(xb + o0);      xp[0]=v.x; xp[1]=v.y;
        v = *(const ulonglong2*)(xb + o0 + 32); xp[2]=v.x; xp[3]=v.y;
        v = *(const ulonglong2*)(ub + o0);      up[0]=v.x; up[1]=v.y;
        v = *(const ulonglong2*)(ub + o0 + 32); up[2]=v.x; up[3]=v.y;
        v = *(const ulonglong2*)(prec + o0);      pp[0]=v.x; pp[1]=v.y;
        v = *(const ulonglong2*)(prec + o0 + 32); pp[2]=v.x; pp[3]=v.y;
    }
    float r   = 0.0f;
    float us  = 1.0f;                              // true u = us * up (deferred renorm)
    float un2 = 1.0f;                              // |up|^2 (u0 is unit)

    const size_t BD  = (size_t)B*64;
    const size_t blk = (size_t)(n_steps+1)*BD;
    float* px = out +           (size_t)row*64;    // traj_x
    float* pu = out +   blk +   (size_t)row*64;    // traj_u
    float* pr = out + 2*blk +   (size_t)row;       // traj_r

    // cached gradient scalars (pure functions of current x)
    float ggc, invg, gnorm, tq;

    // plain write-back stores: let L2 assemble full 128B lines
#define STORE2(A0, A1, GP) \
        asm volatile("st.global.v2.u64 [%0], {%1,%2};" \
                     :: "l"((GP) + o0), "l"(A0), "l"(A1) : "memory")

    // scalar section + u update: uses cached ggc/invg/gnorm/tq and reduced ug.
    // u-norm computed ANALYTICALLY: |c1*g + c2s*u|^2 = c1^2*gg + 2*c1*c2s*ug
    //                                                + c2s^2*|u|^2
#define APPLY(UG) do {                                                       \
        float ude   = -((UG)*us)*invg;                                       \
        float Bc    = 2.0f*tq;                                               \
        float A2    = (ude-1.0f)*(tq*tq);                                    \
        float A     = 1.0f + ude + A2;                                       \
        bool  cond  = ude > -0.999f;                                         \
        float c1    = cond ? invg*fmaf(Bc,ude,-A) : invg;                    \
        float c2s   = (cond ? Bc : 0.0f) * us;                               \
        float Z     = 1.0f + ude - A2;                                       \
        float dr    = cond ? fmaf(ed,gnorm,                                  \
                           LN2*lg2f(fmaxf(0.5f*Z, 5e-11f)))                  \
                           : -ed*gnorm;                                      \
        r += dr;                                                             \
        un2 = fmaf(c1*c1, ggc, fmaf(2.0f*c1*c2s, (UG), c2s*c2s*un2));        \
        un2 = fmaxf(un2, 1e-20f);                                            \
        us  = rsqf(un2);                                                     \
        ull c1p=f2pack(c1), c2p=f2pack(c2s);                                 \
        _Pragma("unroll")                                                    \
        for (int j=0;j<4;j++)                                                \
            up[j] = f2fma(c1p, gr[j], f2mul(c2p, up[j]));                    \
    } while(0)

    // half-step with gradient scalars already cached (x unchanged since they
    // were computed): only the u.g reduction is needed
#define HALF_CACHED() do {                                                   \
        ull gr[4];                                                           \
        ull ug2=0;                                                           \
        _Pragma("unroll")                                                    \
        for (int j=0;j<4;j++){                                               \
            gr[j] = f2mul(pp[j], xp[j]);                                     \
            ug2 = f2fma(up[j],gr[j],ug2);                                    \
        }                                                                    \
        float2 qb=f2unpack(ug2);                                             \
        float ug = red8(qb.x+qb.y);                                          \
        APPLY(ug);                                                           \
    } while(0)

    // half-step after x changed: compute gg & ug together (interleaved
    // butterfly), refresh cached scalars (valid through the next
    // HALF_CACHED since x doesn't change in between)
#define HALF_FRESH() do {                                                    \
        ull gr[4];                                                           \
        ull gg2=0, ug2=0;                                                    \
        _Pragma("unroll")                                                    \
        for (int j=0;j<4;j++){                                               \
            gr[j] = f2mul(pp[j], xp[j]);                                     \
            gg2 = f2fma(gr[j],gr[j],gg2);                                    \
            ug2 = f2fma(up[j],gr[j],ug2);                                    \
        }                                                                    \
        float2 qa=f2unpack(gg2), qb=f2unpack(ug2);                           \
        float gg = qa.x+qa.y, ug = qb.x+qb.y;                                \
        red8_2(gg, ug);                                                      \
        ggc   = fmaxf(gg, 1e-20f);                                           \
        invg  = rsqf(ggc);                                                   \
        gnorm = fminf(ggc*invg, 10.0f);                                      \
        tq    = ex2f(k1*gnorm);                                              \
        APPLY(ug);                                                           \
    } while(0)

    // ---- step 0 slice: x0, u0, r=0 ----
    STORE2(xp[0], xp[1], px);  STORE2(xp[2], xp[3], px + 32);
    STORE2(up[0], up[1], pu);  STORE2(up[2], up[3], pu + 32);
    if (c == 0) *pr = 0.0f;

    // prologue: gradient scalars at x0
    {
        ull gg2=0;
        #pragma unroll
        for (int j=0;j<4;j++){
            ull g = f2mul(pp[j], xp[j]);
            gg2 = f2fma(g,g,gg2);
        }
        float2 qa=f2unpack(gg2);
        ggc   = fmaxf(red8(qa.x+qa.y), 1e-20f);
        invg  = rsqf(ggc);
        gnorm = fminf(ggc*invg, 10.0f);
        tq    = ex2f(k1*gnorm);
    }

    for (int s=0; s<n_steps; s++){
        HALF_CACHED();                                 // grad(x) cached from prev iter
        {
            ull es = f2pack(eps*us);                   // fold renorm into x-update
            #pragma unroll
            for (int j=0;j<4;j++) xp[j] = f2fma(es, up[j], xp[j]);
        }
        // traj_x for this step is final now: store early so the DRAM latency
        // overlaps HALF_FRESH's compute chain
        px += BD;
        STORE2(xp[0], xp[1], px);  STORE2(xp[2], xp[3], px + 32);
        HALF_FRESH();                                  // grad at new x; caches scalars
        pu += BD; pr += B;
        {
            ull usp = f2pack(us);                      // normalized u for output
            ull n0 = f2mul(up[0], usp), n1 = f2mul(up[1], usp);
            ull m2 = f2mul(up[2], usp), n3 = f2mul(up[3], usp);
            STORE2(n0, n1, pu);  STORE2(m2, n3, pu + 32);
        }
        if (c == 0) *pr = r;
    }

#undef HALF_FRESH
#undef HALF_CACHED
#undef APPLY
#undef STORE2
}

extern "C" void kernel_launch(void* const* d_in, const int* in_sizes, int n_in,
                              void* d_out, int out_size)
{
    const float* x0   = (const float*)d_in[0];
    const float* u0   = (const float*)d_in[1];
    const float* prec = (const float*)d_in[2];
    const float* eps  = (const float*)d_in[3];
    int B = in_sizes[0] / 64;
    long long per_slice = (long long)B * 129;
    int n_steps = (int)((long long)out_size / per_slice) - 1;
    if (n_steps < 0) n_steps = 0;

    // 16 rows per block (128 threads, 8 threads/row)
    esh_kernel<<<B/16, 128>>>(x0, u0, prec, eps, (float*)d_out, B, n_steps);
}

// round 10
// speedup vs baseline: 1.0138x; 1.0138x over previous
#include <cuda_runtime.h>
#include <math.h>

typedef unsigned long long ull;

// ---- packed f32x2 helpers (sm_103a FFMA2 path; ptxas won't auto-fuse) ----
__device__ __forceinline__ ull f2mul(ull a, ull b){
    ull d; asm("mul.rn.f32x2 %0,%1,%2;" : "=l"(d) : "l"(a), "l"(b)); return d;
}
__device__ __forceinline__ ull f2fma(ull a, ull b, ull c){
    ull d; asm("fma.rn.f32x2 %0,%1,%2,%3;" : "=l"(d) : "l"(a), "l"(b), "l"(c)); return d;
}
__device__ __forceinline__ ull f2pack(float a){
    ull d; unsigned r = __float_as_uint(a);
    asm("mov.b64 %0,{%1,%1};" : "=l"(d) : "r"(r)); return d;
}
__device__ __forceinline__ float2 f2unpack(ull a){
    unsigned lo, hi;
    asm("mov.b64 {%0,%1},%2;" : "=r"(lo), "=r"(hi) : "l"(a));
    return make_float2(__uint_as_float(lo), __uint_as_float(hi));
}

// ---- MUFU fast paths ----
__device__ __forceinline__ float rsqf(float x){
    float y; asm("rsqrt.approx.f32 %0,%1;" : "=f"(y) : "f"(x)); return y;
}
__device__ __forceinline__ float ex2f(float x){
    float y; asm("ex2.approx.f32 %0,%1;" : "=f"(y) : "f"(x)); return y;
}
__device__ __forceinline__ float lg2f(float x){
    float y; asm("lg2.approx.f32 %0,%1;" : "=f"(y) : "f"(x)); return y;
}

// reduce across the 8-lane group (lanes 0-7, 8-15, ...)
__device__ __forceinline__ float red8(float v){
    v += __shfl_xor_sync(0xffffffffu, v, 1);
    v += __shfl_xor_sync(0xffffffffu, v, 2);
    v += __shfl_xor_sync(0xffffffffu, v, 4);
    return v;
}
// two interleaved 8-lane reductions (hides SHFL latency)
__device__ __forceinline__ void red8_2(float& a, float& b){
    float a1 = __shfl_xor_sync(0xffffffffu, a, 1);
    float b1 = __shfl_xor_sync(0xffffffffu, b, 1);
    a += a1; b += b1;
    float a2 = __shfl_xor_sync(0xffffffffu, a, 2);
    float b2 = __shfl_xor_sync(0xffffffffu, b, 2);
    a += a2; b += b2;
    float a4 = __shfl_xor_sync(0xffffffffu, a, 4);
    float b4 = __shfl_xor_sync(0xffffffffu, b, 4);
    a += a4; b += b4;
}

#define LOG2E 1.4426950408889634f
#define LN2   0.6931471805599453f

__global__ __launch_bounds__(256)
void esh_kernel(const float* __restrict__ x0,
                const float* __restrict__ u0,
                const float* __restrict__ prec,
                const float* __restrict__ eps_p,
                float* __restrict__ out,
                int B, int n_steps)
{
    const int tid = threadIdx.x;
    const int c   = tid & 7;                       // sub-row lane (0..7)
    const int row = blockIdx.x*32 + (tid >> 3);    // 32 rows per 256-thread block

    const float eps = *eps_p;
    const float ed  = eps * (0.5f/64.0f);          // e/d, e = eps/2, d = 64
    const float k1  = -ed * LOG2E;                 // exp(-ed*g) = ex2(k1*g)

    const int o0 = c*4;                            // cols [c*4,c*4+4) and +32

    // ---- per-thread state: 8 floats x, 8 floats u, 8 floats prec (packed) ----
    ull xp[4], up[4], pp[4];
    {
        const float* xb = x0 + (size_t)row*64;
        const float* ub = u0 + (size_t)row*64;
        ulonglong2 v;
        v = *(const ulonglong2*)(xb + o0);      xp[0]=v.x; xp[1]=v.y;
        v = *(const ulonglong2*)(xb + o0 + 32); xp[2]=v.x; xp[3]=v.y;
        v = *(const ulonglong2*)(ub + o0);      up[0]=v.x; up[1]=v.y;
        v = *(const ulonglong2*)(ub + o0 + 32); up[2]=v.x; up[3]=v.y;
        v = *(const ulonglong2*)(prec + o0);      pp[0]=v.x; pp[1]=v.y;
        v = *(const ulonglong2*)(prec + o0 + 32); pp[2]=v.x; pp[3]=v.y;
    }
    float r   = 0.0f;
    float us  = 1.0f;                              // true u = us * up (deferred renorm)
    float un2 = 1.0f;                              // |up|^2 (u0 is unit)

    const size_t BD  = (size_t)B*64;
    const size_t blk = (size_t)(n_steps+1)*BD;
    float* px = out +           (size_t)row*64;    // traj_x
    float* pu = out +   blk +   (size_t)row*64;    // traj_u
    float* pr = out + 2*blk +   (size_t)row;       // traj_r

    // cached gradient scalars (pure functions of current x)
    float ggc, invg, gnorm, tq;

    // plain write-back stores: let L2 assemble full 128B lines
#define STORE2(A0, A1, GP) \
        asm volatile("st.global.v2.u64 [%0], {%1,%2};" \
                     :: "l"((GP) + o0), "l"(A0), "l"(A1) : "memory")

    // scalar section + u update: uses cached ggc/invg/gnorm/tq and reduced ug.
    // u-norm computed ANALYTICALLY: |c1*g + c2s*u|^2 = c1^2*gg + 2*c1*c2s*ug
    //                                                + c2s^2*|u|^2
#define APPLY(UG) do {                                                       \
        float ude   = -((UG)*us)*invg;                                       \
        float Bc    = 2.0f*tq;                                               \
        float A2    = (ude-1.0f)*(tq*tq);                                    \
        float A     = 1.0f + ude + A2;                                       \
        bool  cond  = ude > -0.999f;                                         \
        float c1    = cond ? invg*fmaf(Bc,ude,-A) : invg;                    \
        float c2s   = (cond ? Bc : 0.0f) * us;                               \
        float Z     = 1.0f + ude - A2;                                       \
        float dr    = cond ? fmaf(ed,gnorm,                                  \
                           LN2*lg2f(fmaxf(0.5f*Z, 5e-11f)))                  \
                           : -ed*gnorm;                                      \
        r += dr;                                                             \
        un2 = fmaf(c1*c1, ggc, fmaf(2.0f*c1*c2s, (UG), c2s*c2s*un2));        \
        un2 = fmaxf(un2, 1e-20f);                                            \
        us  = rsqf(un2);                                                     \
        ull c1p=f2pack(c1), c2p=f2pack(c2s);                                 \
        _Pragma("unroll")                                                    \
        for (int j=0;j<4;j++)                                                \
            up[j] = f2fma(c1p, gr[j], f2mul(c2p, up[j]));                    \
    } while(0)

    // half-step with gradient scalars already cached (x unchanged since they
    // were computed): only the u.g reduction is needed
#define HALF_CACHED() do {                                                   \
        ull gr[4];                                                           \
        ull ug2=0;                                                           \
        _Pragma("unroll")                                                    \
        for (int j=0;j<4;j++){                                               \
            gr[j] = f2mul(pp[j], xp[j]);                                     \
            ug2 = f2fma(up[j],gr[j],ug2);                                    \
        }                                                                    \
        float2 qb=f2unpack(ug2);                                             \
        float ug = red8(qb.x+qb.y);                                          \
        APPLY(ug);                                                           \
    } while(0)

    // half-step after x changed: compute gg & ug together (interleaved
    // butterfly), refresh cached scalars (valid through the next
    // HALF_CACHED since x doesn't change in between)
#define HALF_FRESH() do {                                                    \
        ull gr[4];                                                           \
        ull gg2=0, ug2=0;                                                    \
        _Pragma("unroll")                                                    \
        for (int j=0;j<4;j++){                                               \
            gr[j] = f2mul(pp[j], xp[j]);                                     \
            gg2 = f2fma(gr[j],gr[j],gg2);                                    \
            ug2 = f2fma(up[j],gr[j],ug2);                                    \
        }                                                                    \
        float2 qa=f2unpack(gg2), qb=f2unpack(ug2);                           \
        float gg = qa.x+qa.y, ug = qb.x+qb.y;                                \
        red8_2(gg, ug);                                                      \
        ggc   = fmaxf(gg, 1e-20f);                                           \
        invg  = rsqf(ggc);                                                   \
        gnorm = fminf(ggc*invg, 10.0f);                                      \
        tq    = ex2f(k1*gnorm);                                              \
        APPLY(ug);                                                           \
    } while(0)

    // ---- step 0 slice: x0, u0, r=0 ----
    STORE2(xp[0], xp[1], px);  STORE2(xp[2], xp[3], px + 32);
    STORE2(up[0], up[1], pu);  STORE2(up[2], up[3], pu + 32);
    if (c == 0) *pr = 0.0f;

    // prologue: gradient scalars at x0
    {
        ull gg2=0;
        #pragma unroll
        for (int j=0;j<4;j++){
            ull g = f2mul(pp[j], xp[j]);
            gg2 = f2fma(g,g,gg2);
        }
        float2 qa=f2unpack(gg2);
        ggc   = fmaxf(red8(qa.x+qa.y), 1e-20f);
        invg  = rsqf(ggc);
        gnorm = fminf(ggc*invg, 10.0f);
        tq    = ex2f(k1*gnorm);
    }

    for (int s=0; s<n_steps; s++){
        HALF_CACHED();                                 // grad(x) cached from prev iter
        {
            ull es = f2pack(eps*us);                   // fold renorm into x-update
            #pragma unroll
            for (int j=0;j<4;j++) xp[j] = f2fma(es, up[j], xp[j]);
        }
        // traj_x for this step is final now: store early so the DRAM latency
        // overlaps HALF_FRESH's compute chain
        px += BD;
        STORE2(xp[0], xp[1], px);  STORE2(xp[2], xp[3], px + 32);
        HALF_FRESH();                                  // grad at new x; caches scalars
        pu += BD; pr += B;
        {
            ull usp = f2pack(us);                      // normalized u for output
            ull n0 = f2mul(up[0], usp), n1 = f2mul(up[1], usp);
            ull m2 = f2mul(up[2], usp), n3 = f2mul(up[3], usp);
            STORE2(n0, n1, pu);  STORE2(m2, n3, pu + 32);
        }
        if (c == 0) *pr = r;
    }

#undef HALF_FRESH
#undef HALF_CACHED
#undef APPLY
#undef STORE2
}

extern "C" void kernel_launch(void* const* d_in, const int* in_sizes, int n_in,
                              void* d_out, int out_size)
{
    const float* x0   = (const float*)d_in[0];
    const float* u0   = (const float*)d_in[1];
    const float* prec = (const float*)d_in[2];
    const float* eps  = (const float*)d_in[3];
    int B = in_sizes[0] / 64;
    long long per_slice = (long long)B * 129;
    int n_steps = (int)((long long)out_size / per_slice) - 1;
    if (n_steps < 0) n_steps = 0;

    // 32 rows per block (256 threads, 8 threads/row)
    esh_kernel<<<B/32, 256>>>(x0, u0, prec, eps, (float*)d_out, B, n_steps);
}

// round 11
// speedup vs baseline: 1.0559x; 1.0415x over previous
#include <cuda_runtime.h>
#include <math.h>

typedef unsigned long long ull;

// ---- packed f32x2 helpers (sm_103a FFMA2 path; ptxas won't auto-fuse) ----
__device__ __forceinline__ ull f2mul(ull a, ull b){
    ull d; asm("mul.rn.f32x2 %0,%1,%2;" : "=l"(d) : "l"(a), "l"(b)); return d;
}
__device__ __forceinline__ ull f2fma(ull a, ull b, ull c){
    ull d; asm("fma.rn.f32x2 %0,%1,%2,%3;" : "=l"(d) : "l"(a), "l"(b), "l"(c)); return d;
}
__device__ __forceinline__ ull f2pack(float a){
    ull d; unsigned r = __float_as_uint(a);
    asm("mov.b64 %0,{%1,%1};" : "=l"(d) : "r"(r)); return d;
}
__device__ __forceinline__ float2 f2unpack(ull a){
    unsigned lo, hi;
    asm("mov.b64 {%0,%1},%2;" : "=r"(lo), "=r"(hi) : "l"(a));
    return make_float2(__uint_as_float(lo), __uint_as_float(hi));
}

// ---- MUFU fast paths ----
__device__ __forceinline__ float rsqf(float x){
    float y; asm("rsqrt.approx.f32 %0,%1;" : "=f"(y) : "f"(x)); return y;
}
__device__ __forceinline__ float ex2f(float x){
    float y; asm("ex2.approx.f32 %0,%1;" : "=f"(y) : "f"(x)); return y;
}
__device__ __forceinline__ float lg2f(float x){
    float y; asm("lg2.approx.f32 %0,%1;" : "=f"(y) : "f"(x)); return y;
}

// reduce across the 8-lane group (lanes 0-7, 8-15, ...)
__device__ __forceinline__ float red8(float v){
    v += __shfl_xor_sync(0xffffffffu, v, 1);
    v += __shfl_xor_sync(0xffffffffu, v, 2);
    v += __shfl_xor_sync(0xffffffffu, v, 4);
    return v;
}

#define LOG2E 1.4426950408889634f
#define LN2   0.6931471805599453f

__global__ __launch_bounds__(256)
void esh_kernel(const float* __restrict__ x0,
                const float* __restrict__ u0,
                const float* __restrict__ prec,
                const float* __restrict__ eps_p,
                float* __restrict__ out,
                int B, int n_steps)
{
    const int tid = threadIdx.x;
    const int c   = tid & 7;                       // sub-row lane (0..7)
    const int row = blockIdx.x*32 + (tid >> 3);    // 32 rows per 256-thread block

    const float eps = *eps_p;
    const float ed  = eps * (0.5f/64.0f);          // e/d, e = eps/2, d = 64
    const float k1  = -ed * LOG2E;                 // exp(-ed*g) = ex2(k1*g)

    // column offsets (floats): cols [c*4, c*4+4) and [32+c*4, 32+c*4+4)
    const int o0 = c*4, o1 = 32 + c*4;

    // ---- per-thread state: 8 floats x, 8 floats u, 8 floats prec (packed) ----
    ull xp[4], up[4], pp[4];
    {
        const float* xb = x0 + (size_t)row*64;
        const float* ub = u0 + (size_t)row*64;
        ulonglong2 v;
        v = *(const ulonglong2*)(xb + o0); xp[0]=v.x; xp[1]=v.y;
        v = *(const ulonglong2*)(xb + o1); xp[2]=v.x; xp[3]=v.y;
        v = *(const ulonglong2*)(ub + o0); up[0]=v.x; up[1]=v.y;
        v = *(const ulonglong2*)(ub + o1); up[2]=v.x; up[3]=v.y;
        v = *(const ulonglong2*)(prec + o0); pp[0]=v.x; pp[1]=v.y;
        v = *(const ulonglong2*)(prec + o1); pp[2]=v.x; pp[3]=v.y;
    }
    float r  = 0.0f;
    float us = 1.0f;                               // true u = us * up (deferred renorm)

    const size_t BD  = (size_t)B*64;
    const size_t blk = (size_t)(n_steps+1)*BD;
    float* px = out +           (size_t)row*64;    // traj_x
    float* pu = out +   blk +   (size_t)row*64;    // traj_u
    float* pr = out + 2*blk +   (size_t)row;       // traj_r

    // perfectly coalesced streaming register stores (evict-first: never re-read,
    // and keeps L2 clean across graph replays -> better steady-state bench time)
#define STORE2(A0, A1, GP) do {                                          \
        __stcs((ulonglong2*)((GP) + o0), make_ulonglong2((A0), (A1)));   \
    } while(0)

    // HALF_STEP: consumes xp (positions), up+us (scaled direction); updates up, us, r
#define HALF_STEP() do {                                                     \
        ull gr[4];                                                           \
        ull gg2=0, ug2=0;                                                    \
        _Pragma("unroll")                                                    \
        for (int j=0;j<4;j++){                                               \
            gr[j] = f2mul(pp[j], xp[j]);                                     \
            gg2 = f2fma(gr[j],gr[j],gg2);                                    \
            ug2 = f2fma(up[j],gr[j],ug2);                                    \
        }                                                                    \
        float2 qa=f2unpack(gg2), qb=f2unpack(ug2);                           \
        float gg = red8(qa.x+qa.y);                                          \
        float ug = red8(qb.x+qb.y);                                          \
        gg = fmaxf(gg, 1e-20f);                                              \
        float invg  = rsqf(gg);                                              \
        float gn0   = gg*invg;                     /* = sqrt(gg) >= 1e-10 */ \
        float gnorm = fminf(gn0, 10.0f);                                     \
        float ude   = -(ug*us)*invg;                                         \
        float t     = ex2f(k1*gnorm);                                        \
        float Bc    = 2.0f*t;                                                \
        float A2    = (ude-1.0f)*(t*t);                                      \
        float A     = 1.0f + ude + A2;                                       \
        bool  cond  = ude > -0.999f;                                         \
        float c1    = cond ? invg*fmaf(Bc,ude,-A) : invg;                    \
        float c2s   = (cond ? Bc : 0.0f) * us;                               \
        float Z     = 1.0f + ude - A2;                                       \
        float dr    = cond ? fmaf(ed,gnorm,                                  \
                           LN2*lg2f(fmaxf(0.5f*Z, 5e-11f)))                  \
                           : -ed*gnorm;                                      \
        r += dr;                                                             \
        ull c1p=f2pack(c1), c2p=f2pack(c2s);                                 \
        ull n2=0;                                                            \
        _Pragma("unroll")                                                    \
        for (int j=0;j<4;j++){                                               \
            ull tn = f2fma(c1p, gr[j], f2mul(c2p, up[j]));                   \
            up[j]=tn; n2 = f2fma(tn,tn,n2);                                  \
        }                                                                    \
        float2 qn=f2unpack(n2);                                              \
        float un2 = red8(qn.x+qn.y);                                         \
        us = rsqf(fmaxf(un2, 1e-20f));                                       \
    } while(0)

    // ---- step 0 slice: x0, u0 (already unit), r=0 ----
    STORE2(xp[0], xp[1], px);  STORE2(xp[2], xp[3], px + 32);
    STORE2(up[0], up[1], pu);  STORE2(up[2], up[3], pu + 32);
    if (c == 0) *pr = 0.0f;

    for (int s=0; s<n_steps; s++){
        HALF_STEP();                                   // first half (e = eps/2)
        {
            ull es = f2pack(eps*us);                   // fold renorm into x-update
            #pragma unroll
            for (int j=0;j<4;j++) xp[j] = f2fma(es, up[j], xp[j]);
        }
        HALF_STEP();                                   // second half
        px += BD; pu += BD; pr += B;
        STORE2(xp[0], xp[1], px);  STORE2(xp[2], xp[3], px + 32);
        {
            ull usp = f2pack(us);                      // normalized u for output
            ull n0 = f2mul(up[0], usp), n1 = f2mul(up[1], usp);
            ull n2_ = f2mul(up[2], usp), n3 = f2mul(up[3], usp);
            STORE2(n0, n1, pu);  STORE2(n2_, n3, pu + 32);
        }
        if (c == 0) *pr = r;
    }

#undef HALF_STEP
#undef STORE2
}

extern "C" void kernel_launch(void* const* d_in, const int* in_sizes, int n_in,
                              void* d_out, int out_size)
{
    const float* x0   = (const float*)d_in[0];
    const float* u0   = (const float*)d_in[1];
    const float* prec = (const float*)d_in[2];
    const float* eps  = (const float*)d_in[3];
    int B = in_sizes[0] / 64;
    long long per_slice = (long long)B * 129;
    int n_steps = (int)((long long)out_size / per_slice) - 1;
    if (n_steps < 0) n_steps = 0;

    // 32 rows per block (256 threads, 8 threads/row)
    esh_kernel<<<B/32, 256>>>(x0, u0, prec, eps, (float*)d_out, B, n_steps);
}